// round 10
// baseline (speedup 1.0000x reference)
#include <cuda_runtime.h>
#include <cstdint>
#include <math.h>

#define BATCH   2048
#define IN_DIM  512
#define NUM_OUT 256

#define BM 32
#define BN 128
#define BK 16
#define NTHREADS 128
#define KSPLIT 4
#define KCHUNK (IN_DIM / KSPLIT)    // 128
#define NSTEPS (KCHUNK / BK)        // 8

typedef unsigned long long ull;

// g_w[k][o] = -sigmoid(5 * W_raw[o][k]); [512][256] floats, 512 KB.
__device__ float g_w[IN_DIM * NUM_OUT];
// Partial products per K-chunk: 8 MB
__device__ float g_part[KSPLIT][BATCH * NUM_OUT];

// float4 along k per thread (MLP=4, coalesced loads); 4 scattered 4B stores
// are fire-and-forget.
__global__ void precompute_kernel(const float* __restrict__ Wraw) {
    int i = blockIdx.x * blockDim.x + threadIdx.x;   // 0 .. 32767
    if (i < NUM_OUT * (IN_DIM / 4)) {
        int o  = i >> 7;          // 0..255
        int k4 = (i & 127) * 4;   // 0,4,...,508
        float4 v = *reinterpret_cast<const float4*>(&Wraw[o * IN_DIM + k4]);
        g_w[(k4 + 0) * NUM_OUT + o] = -1.0f / (1.0f + __expf(-5.0f * v.x));
        g_w[(k4 + 1) * NUM_OUT + o] = -1.0f / (1.0f + __expf(-5.0f * v.y));
        g_w[(k4 + 2) * NUM_OUT + o] = -1.0f / (1.0f + __expf(-5.0f * v.z));
        g_w[(k4 + 3) * NUM_OUT + o] = -1.0f / (1.0f + __expf(-5.0f * v.w));
    }
}

__device__ __forceinline__ ull ffma2(ull a, ull b, ull c) {
    ull d;
    asm("fma.rn.f32x2 %0, %1, %2, %3;" : "=l"(d) : "l"(a), "l"(b), "l"(c));
    return d;
}
__device__ __forceinline__ ull fmul2(ull a, ull b) {
    ull d;
    asm("mul.rn.f32x2 %0, %1, %2;" : "=l"(d) : "l"(a), "l"(b));
    return d;
}
__device__ __forceinline__ void cp_async16(uint32_t smem, const void* gptr) {
    asm volatile("cp.async.cg.shared.global [%0], [%1], 16;" :: "r"(smem), "l"(gptr));
}

// Self-contained x-duplication store: xs[b][kb+slot][2*xm] = (1-val, 1-val)
#define XDUP(b, slot, val) do {                                            \
    float2 _p; _p.x = 1.0f - (val); _p.y = _p.x;                           \
    *reinterpret_cast<float2*>(&xs[b][kb + (slot)][2 * xm]) = _p;          \
} while (0)

// 32(M) x 128(N) tile per CTA over one 128-K chunk. Thread tile 4x8.
// Accumulator packs two adjacent N-cols per f32x2 (no w duplication).
// x stored duplicated in smem: xs[k][2*row] = xs[k][2*row+1] = 1-x.
// w row piece-permuted: 16B piece p -> phys chunk (p even ? p/2 : 16+p/2),
// so each thread's two LDS.128 hit contiguous 256B halves (conflict-free).
__global__ void __launch_bounds__(NTHREADS, 4)
logic_kernel(const float* __restrict__ x) {
    __shared__ __align__(16) float xs[2][BK][2 * BM + 4];   // 68 floats/row
    __shared__ __align__(16) float ws[2][BK][BN + 4];       // 132 floats/row

    const int tid = threadIdx.x;
    const int bm0 = blockIdx.x * BM;
    const int bn  = blockIdx.y;          // 0..1
    const int kz  = blockIdx.z;          // K-chunk
    const int kbase = kz * KCHUNK;

    const int cg = tid & 15;   // col-group: 8 cols each
    const int rg = tid >> 4;   // row-group: 4 rows each (8 groups x 4 = 32)

    // x staging: row xm (0..31), k-quarter xq (4 k's each)
    const int xm = tid & 31;
    const int xq = tid >> 5;   // 0..3
    const int kb = xq * 4;

    const ull ONE2 = 0x3F8000003F800000ULL;
    ull acc[4][4];
#pragma unroll
    for (int i = 0; i < 4; ++i)
#pragma unroll
        for (int j = 0; j < 4; ++j) acc[i][j] = ONE2;

    const float* xrow = x + (ull)(bm0 + xm) * IN_DIM + kbase + xq * 4;

    // ---------------- prologue: fill buffer 0 ----------------
    {
        float4 a = *reinterpret_cast<const float4*>(xrow);
        // w tile: 16 rows x 32 chunks of 16B = 512 chunks, 4 per thread
#pragma unroll
        for (int c = 0; c < 4; ++c) {
            int idx = c * 128 + tid;
            int k   = idx >> 5;        // 0..15
            int q   = idx & 31;        // 16B chunk within row
            int goff = ((q & 15) * 8 + (q >> 4) * 4);
            const float* src = g_w + (ull)(kbase + k) * NUM_OUT + bn * BN + goff;
            cp_async16((uint32_t)__cvta_generic_to_shared(&ws[0][k][q * 4]), src);
        }
        asm volatile("cp.async.commit_group;" ::: "memory");
        XDUP(0, 0, a.x); XDUP(0, 1, a.y); XDUP(0, 2, a.z); XDUP(0, 3, a.w);
    }

    // ---------------- main loop ----------------
    for (int step = 0; step < NSTEPS; ++step) {
        const int buf  = step & 1;
        const int nbuf = buf ^ 1;
        const bool more = (step + 1 < NSTEPS);

        __syncthreads();   // compute(step-1) done; x STS(step) visible

        float4 a;
        if (more) {
            a = *reinterpret_cast<const float4*>(xrow + (step + 1) * BK);
            int k0 = kbase + (step + 1) * BK;
#pragma unroll
            for (int c = 0; c < 4; ++c) {
                int idx = c * 128 + tid;
                int k   = idx >> 5;
                int q   = idx & 31;
                int goff = ((q & 15) * 8 + (q >> 4) * 4);
                const float* src = g_w + (ull)(k0 + k) * NUM_OUT + bn * BN + goff;
                cp_async16((uint32_t)__cvta_generic_to_shared(&ws[nbuf][k][q * 4]), src);
            }
        }
        asm volatile("cp.async.commit_group;" ::: "memory");
        asm volatile("cp.async.wait_group 1;" ::: "memory");
        __syncthreads();   // ws[buf] fully landed

        // ---------- compute on buf ----------
#pragma unroll
        for (int k = 0; k < BK; ++k) {
            // x: 4 duplicated pairs for rows rg*4 .. rg*4+3 (contiguous 32B)
            ulonglong2 xa = *reinterpret_cast<const ulonglong2*>(&xs[buf][k][rg * 8]);
            ulonglong2 xb = *reinterpret_cast<const ulonglong2*>(&xs[buf][k][rg * 8 + 4]);
            // w: cols cg*8..cg*8+7 -> phys chunks cg (0..3) and 16+cg (4..7)
            ulonglong2 wa = *reinterpret_cast<const ulonglong2*>(&ws[buf][k][cg * 4]);
            ulonglong2 wb = *reinterpret_cast<const ulonglong2*>(&ws[buf][k][64 + cg * 4]);
            ull xv[4] = {xa.x, xa.y, xb.x, xb.y};
            ull wv[4] = {wa.x, wa.y, wb.x, wb.y};
#pragma unroll
            for (int i = 0; i < 4; ++i) {
#pragma unroll
                for (int j = 0; j < 4; ++j) {
                    ull z = ffma2(wv[j], xv[i], ONE2);   // (1-w*t, 1-w*t)
                    acc[i][j] = fmul2(acc[i][j], z);
                }
            }
        }

        if (more) {
            XDUP(nbuf, 0, a.x); XDUP(nbuf, 1, a.y); XDUP(nbuf, 2, a.z); XDUP(nbuf, 3, a.w);
        }
    }

    // ---------------- epilogue: write partial products ----------------
    float* orow = g_part[kz] + (ull)(bm0 + rg * 4) * NUM_OUT + bn * BN + cg * 8;
#pragma unroll
    for (int i = 0; i < 4; ++i) {
        float4 v0, v1;
        v0.x = __uint_as_float((unsigned)(acc[i][0]));
        v0.y = __uint_as_float((unsigned)(acc[i][0] >> 32));
        v0.z = __uint_as_float((unsigned)(acc[i][1]));
        v0.w = __uint_as_float((unsigned)(acc[i][1] >> 32));
        v1.x = __uint_as_float((unsigned)(acc[i][2]));
        v1.y = __uint_as_float((unsigned)(acc[i][2] >> 32));
        v1.z = __uint_as_float((unsigned)(acc[i][3]));
        v1.w = __uint_as_float((unsigned)(acc[i][3] >> 32));
        *reinterpret_cast<float4*>(orow + (ull)i * NUM_OUT)     = v0;
        *reinterpret_cast<float4*>(orow + (ull)i * NUM_OUT + 4) = v1;
    }
}

// out = p0 * p1 * p2 * p3 elementwise (float4-vectorized)
__global__ void combine_kernel(float* __restrict__ out) {
    int i = blockIdx.x * blockDim.x + threadIdx.x;
    if (i < (BATCH * NUM_OUT) / 4) {
        float4 a = reinterpret_cast<const float4*>(g_part[0])[i];
        float4 b = reinterpret_cast<const float4*>(g_part[1])[i];
        float4 c = reinterpret_cast<const float4*>(g_part[2])[i];
        float4 d = reinterpret_cast<const float4*>(g_part[3])[i];
        float4 v;
        v.x = (a.x * b.x) * (c.x * d.x);
        v.y = (a.y * b.y) * (c.y * d.y);
        v.z = (a.z * b.z) * (c.z * d.z);
        v.w = (a.w * b.w) * (c.w * d.w);
        reinterpret_cast<float4*>(out)[i] = v;
    }
}

extern "C" void kernel_launch(void* const* d_in, const int* in_sizes, int n_in,
                              void* d_out, int out_size) {
    const float* x    = (const float*)d_in[0];   // [2048, 512]
    const float* Wraw = (const float*)d_in[1];   // [256, 512]
    float* out        = (float*)d_out;           // [2048, 256]

    precompute_kernel<<<(NUM_OUT * (IN_DIM / 4) + 127) / 128, 128>>>(Wraw);

    dim3 grid(BATCH / BM, NUM_OUT / BN, KSPLIT); // 64 x 2 x 4 = 512 CTAs
    logic_kernel<<<grid, NTHREADS>>>(x);

    combine_kernel<<<(BATCH * NUM_OUT / 4 + 255) / 256, 256>>>(out);
}